// round 3
// baseline (speedup 1.0000x reference)
#include <cuda_runtime.h>
#include <cstdint>

#define N_NODES 10000
#define N_EDGES 320000
#define CH 64
#define TE 128          // edges (CSR positions) per block in fused edge kernel
#define AP 76           // activation smem pitch (conflict-free A-frag loads)
#define WP 68           // weight smem pitch (conflict-free B-frag loads)

// ---------------- scratch (device globals; allocation-free) ----------------
__device__ float g_h[N_NODES * CH];                 // 2.56 MB
__device__ float g_agg[(size_t)N_NODES * 9 * 64];   // 23 MB: [n][k][c]
__device__ int   g_count[N_NODES];
__device__ int   g_rowstart[N_NODES + 1];
__device__ int   g_cursor[N_NODES];
__device__ int   g_csr[N_EDGES];                    // pos -> edge id
__device__ int   g_send[N_EDGES];                   // pos -> sender node
__device__ int   g_recv[N_EDGES];                   // pos -> receiver node

__device__ __forceinline__ float silu_f(float x) {
    return x / (1.f + __expf(-x));
}

__device__ __forceinline__ uint32_t f2tf32(float f) {
    uint32_t r;
    asm("cvt.rna.tf32.f32 %0, %1;" : "=r"(r) : "f"(f));
    return r;
}

__device__ __forceinline__ void mma_tf32(float acc[4], uint32_t a0, uint32_t a1,
                                         uint32_t a2, uint32_t a3,
                                         uint32_t b0, uint32_t b1) {
    asm volatile(
        "mma.sync.aligned.m16n8k8.row.col.f32.tf32.tf32.f32 "
        "{%0,%1,%2,%3}, {%4,%5,%6,%7}, {%8,%9}, {%0,%1,%2,%3};\n"
        : "+f"(acc[0]), "+f"(acc[1]), "+f"(acc[2]), "+f"(acc[3])
        : "r"(a0), "r"(a1), "r"(a2), "r"(a3), "r"(b0), "r"(b1));
}

// ---------------- h = (node_feats @ W_up) / 8 ----------------
__global__ __launch_bounds__(256) void k_h(const float* __restrict__ nf,
                                           const float* __restrict__ Wup) {
    __shared__ float sW[64 * 64];
    __shared__ float sN[4 * 64];
    int t = threadIdx.x;
    for (int idx = t; idx < 1024; idx += 256)
        ((float4*)sW)[idx] = ((const float4*)Wup)[idx];
    int n0 = blockIdx.x * 4;
    if (t < 64)
        ((float4*)sN)[t] = ((const float4*)(nf + (size_t)n0 * 64))[t];
    __syncthreads();
    int i = t >> 6, c = t & 63;
    float a0 = 0.f, a1 = 0.f;
#pragma unroll
    for (int k = 0; k < 64; k += 2) {
        a0 = fmaf(sN[i * 64 + k],     sW[k * 64 + c],       a0);
        a1 = fmaf(sN[i * 64 + k + 1], sW[(k + 1) * 64 + c], a1);
    }
    g_h[(size_t)(n0 + i) * 64 + c] = (a0 + a1) * 0.125f;
}

// ---------------- CSR build ----------------
__global__ void k_zero() {
    int i = blockIdx.x * blockDim.x + threadIdx.x;
    if (i < N_NODES) g_count[i] = 0;
}

__global__ void k_zeroagg() {
    int i = blockIdx.x * blockDim.x + threadIdx.x;   // float4 granularity
    if (i < N_NODES * 9 * 64 / 4)
        ((float4*)g_agg)[i] = make_float4(0.f, 0.f, 0.f, 0.f);
}

__global__ void k_count(const int* __restrict__ recv) {
    int e = blockIdx.x * blockDim.x + threadIdx.x;
    if (e < N_EDGES) atomicAdd(&g_count[recv[e]], 1);
}

__global__ __launch_bounds__(256) void k_scan() {
    __shared__ int part[256];
    int t = threadIdx.x;
    int base = t * 40;
    int s = 0;
    for (int i = 0; i < 40; ++i) {
        int idx = base + i;
        if (idx < N_NODES) s += g_count[idx];
    }
    part[t] = s;
    __syncthreads();
    if (t == 0) {
        int run = 0;
        for (int i = 0; i < 256; ++i) { int v = part[i]; part[i] = run; run += v; }
    }
    __syncthreads();
    int run = part[t];
    for (int i = 0; i < 40; ++i) {
        int idx = base + i;
        if (idx < N_NODES) {
            g_rowstart[idx] = run;
            g_cursor[idx] = run;
            run += g_count[idx];
        }
    }
    if (t == 255) g_rowstart[N_NODES] = run;
}

__global__ void k_fill(const int* __restrict__ recv, const int* __restrict__ send) {
    int e = blockIdx.x * blockDim.x + threadIdx.x;
    if (e < N_EDGES) {
        int r = recv[e];
        int pos = atomicAdd(&g_cursor[r], 1);
        g_csr[pos] = e;
        g_send[pos] = send[e];
        g_recv[pos] = r;
    }
}

// ---------------- fused: radial MLP (tf32 mma) + SH + tensor product + scatter ----------------
// Block: 128 CSR positions, 256 threads = 8 warps. Warp w owns rows [16w, 16w+16).

__device__ __forceinline__ void load_w64(uint32_t* __restrict__ sW,
                                         const float* __restrict__ gW, int t) {
    for (int idx = t; idx < 4096; idx += 256) {
        int k = idx >> 6, n = idx & 63;
        sW[n * WP + k] = f2tf32(gW[idx]);
    }
}

template <int KSTEPS>
__device__ __forceinline__ void mma_layer(const uint32_t* __restrict__ sIn,
                                          const uint32_t* __restrict__ sW,
                                          float acc[8][4],
                                          int slab, int gid, int tid4) {
#pragma unroll
    for (int nt = 0; nt < 8; ++nt) {
        acc[nt][0] = 0.f; acc[nt][1] = 0.f; acc[nt][2] = 0.f; acc[nt][3] = 0.f;
    }
#pragma unroll
    for (int kk = 0; kk < KSTEPS; ++kk) {
        int c0 = kk * 8 + tid4;
        uint32_t a0 = sIn[(slab + gid) * AP + c0];
        uint32_t a1 = sIn[(slab + gid + 8) * AP + c0];
        uint32_t a2 = sIn[(slab + gid) * AP + c0 + 4];
        uint32_t a3 = sIn[(slab + gid + 8) * AP + c0 + 4];
#pragma unroll
        for (int nt = 0; nt < 8; ++nt) {
            uint32_t b0 = sW[(nt * 8 + gid) * WP + c0];
            uint32_t b1 = sW[(nt * 8 + gid) * WP + c0 + 4];
            mma_tf32(acc[nt], a0, a1, a2, a3, b0, b1);
        }
    }
}

__device__ __forceinline__ void store_act_mma(uint32_t* __restrict__ sOut,
                                              float acc[8][4], float scale,
                                              int slab, int gid, int tid4) {
#pragma unroll
    for (int nt = 0; nt < 8; ++nt) {
        int col = nt * 8 + 2 * tid4;
        uint32_t t0 = f2tf32(silu_f(acc[nt][0] * scale));
        uint32_t t1 = f2tf32(silu_f(acc[nt][1] * scale));
        uint32_t t2 = f2tf32(silu_f(acc[nt][2] * scale));
        uint32_t t3 = f2tf32(silu_f(acc[nt][3] * scale));
        *(uint2*)(sOut + (slab + gid) * AP + col)     = make_uint2(t0, t1);
        *(uint2*)(sOut + (slab + gid + 8) * AP + col) = make_uint2(t2, t3);
    }
}

// smem layout (32-bit words)
#define O_SA    0
#define O_SB    9728
#define O_SW    19456            // 64*WP = 4352
#define O_SH    23808            // h tile [128][66] floats
#define O_MSG   32256            // msg tile [128][66] floats
#define O_SSH   40704            // sh [128][12] floats
#define O_RECV  42240            // recv ids [128]
#define SMEM_EDGE_WORDS (42368)

template <int D, int KOFF, int CHK>
__device__ __forceinline__ void l4_chunk(uint32_t* __restrict__ sW,
                                         const uint32_t* __restrict__ sB,
                                         const float* __restrict__ sH,
                                         float* __restrict__ sMsg,
                                         const float* __restrict__ sSh,
                                         const int* __restrict__ sRecv,
                                         const float* __restrict__ W4,
                                         int t, int slab, int gid, int tid4) {
    // load W4 chunk (cols [CHK*64, CHK*64+64)), transposed
    for (int idx = t; idx < 4096; idx += 256) {
        int k = idx >> 6, n = idx & 63;
        sW[n * WP + k] = f2tf32(W4[(size_t)k * 192 + CHK * 64 + n]);
    }
    __syncthreads();

    float acc[8][4];
    mma_layer<8>(sB, sW, acc, slab, gid, tid4);

    // multiply by h and scale (1/sqrt(64) * 1/avg_neigh = 1/256), stage msg
    const float S = 1.f / 256.f;
#pragma unroll
    for (int nt = 0; nt < 8; ++nt) {
        int col = nt * 8 + 2 * tid4;
        int r0 = slab + gid, r1 = r0 + 8;
        float2 h0 = *(const float2*)(sH + r0 * 66 + col);
        float2 h1 = *(const float2*)(sH + r1 * 66 + col);
        *(float2*)(sMsg + r0 * 66 + col) =
            make_float2(acc[nt][0] * h0.x * S, acc[nt][1] * h0.y * S);
        *(float2*)(sMsg + r1 * 66 + col) =
            make_float2(acc[nt][2] * h1.x * S, acc[nt][3] * h1.y * S);
    }
    __syncthreads();

    // segment reduction over rows; atomic flush per receiver run
    {
        int c = t & 63, q = t >> 6;
        int rbase = q * 32;
        int ncur = sRecv[rbase];
        float a[D];
#pragma unroll
        for (int k = 0; k < D; ++k) a[k] = 0.f;
        for (int r = 0; r < 32; ++r) {
            int row = rbase + r;
            int n = sRecv[row];
            if (n != ncur) {
#pragma unroll
                for (int k = 0; k < D; ++k) {
                    atomicAdd(&g_agg[(size_t)(ncur * 9 + KOFF + k) * 64 + c], a[k]);
                    a[k] = 0.f;
                }
                ncur = n;
            }
            float m = sMsg[row * 66 + c];
#pragma unroll
            for (int k = 0; k < D; ++k)
                a[k] = fmaf(m, sSh[row * 12 + KOFF + k], a[k]);
        }
#pragma unroll
        for (int k = 0; k < D; ++k)
            atomicAdd(&g_agg[(size_t)(ncur * 9 + KOFF + k) * 64 + c], a[k]);
    }
    __syncthreads();
}

__global__ __launch_bounds__(256) void k_edge(const float* __restrict__ evec,
                                              const float* __restrict__ rad,
                                              const float* __restrict__ W1,
                                              const float* __restrict__ W2,
                                              const float* __restrict__ W3,
                                              const float* __restrict__ W4) {
    extern __shared__ uint32_t sm[];
    uint32_t* sA = sm + O_SA;            // [128][AP] tf32
    uint32_t* sB = sm + O_SB;            // [128][AP] tf32
    uint32_t* sW = sm + O_SW;            // [64][WP] tf32
    float* sH    = (float*)(sm + O_SH);  // [128][66]
    float* sMsg  = (float*)(sm + O_MSG); // [128][66]
    float* sSh   = (float*)(sm + O_SSH); // [128][12]
    int*   sRecv = (int*)(sm + O_RECV);  // [128]

    int t = threadIdx.x;
    int lane = t & 31, warp = t >> 5;
    int gid = lane >> 2, tid4 = lane & 3, slab = warp * 16;
    int pos_base = blockIdx.x * TE;

    // per-position: SH + radial + recv (CSR order)
    if (t < TE) {
        int pos = pos_base + t;
        int e = g_csr[pos];
        sRecv[t] = g_recv[pos];

        float x = evec[(size_t)e * 3], y = evec[(size_t)e * 3 + 1],
              z = evec[(size_t)e * 3 + 2];
        float rn = rsqrtf(x * x + y * y + z * z);
        x *= rn; y *= rn; z *= rn;
        const float c3  = 1.7320508075688772f;
        const float c15 = 3.872983346207417f;
        const float c5h = 1.118033988749895f;
        const float c15h= 1.9364916731037085f;
        float* o = sSh + t * 12;
        o[0] = 1.f;
        o[1] = c3 * x; o[2] = c3 * y; o[3] = c3 * z;
        o[4] = c15 * x * y; o[5] = c15 * y * z;
        o[6] = c5h * (3.f * z * z - 1.f);
        o[7] = c15 * x * z; o[8] = c15h * (x * x - y * y);

        float4 r0 = *(const float4*)(rad + (size_t)e * 8);
        float4 r1 = *(const float4*)(rad + (size_t)e * 8 + 4);
        uint32_t* dst = sA + t * AP;
        dst[0] = f2tf32(r0.x); dst[1] = f2tf32(r0.y);
        dst[2] = f2tf32(r0.z); dst[3] = f2tf32(r0.w);
        dst[4] = f2tf32(r1.x); dst[5] = f2tf32(r1.y);
        dst[6] = f2tf32(r1.z); dst[7] = f2tf32(r1.w);
    }
    // h tile: gather rows of g_h for this block's senders
    for (int idx = t; idx < 128 * 32; idx += 256) {
        int row = idx >> 5, c2 = idx & 31;
        int s = g_send[pos_base + row];
        *(float2*)(sH + row * 66 + c2 * 2) =
            *(const float2*)(g_h + (size_t)s * 64 + c2 * 2);
    }
    // W1: [8][64] -> sW[n][k]
    for (int idx = t; idx < 512; idx += 256) {
        int k = idx >> 6, n = idx & 63;
        sW[n * WP + k] = f2tf32(W1[idx]);
    }
    __syncthreads();

    float acc[8][4];

    // L1: [128,8] @ [8,64]
    mma_layer<1>(sA, sW, acc, slab, gid, tid4);
    store_act_mma(sB, acc, 0.35355339059327373f, slab, gid, tid4);
    __syncthreads();

    // L2
    load_w64(sW, W2, t);
    __syncthreads();
    mma_layer<8>(sB, sW, acc, slab, gid, tid4);
    store_act_mma(sA, acc, 0.125f, slab, gid, tid4);
    __syncthreads();

    // L3
    load_w64(sW, W3, t);
    __syncthreads();
    mma_layer<8>(sA, sW, acc, slab, gid, tid4);
    store_act_mma(sB, acc, 0.125f, slab, gid, tid4);
    __syncthreads();

    // L4 + tensor product + segment scatter, one l at a time
    l4_chunk<1, 0, 0>(sW, sB, sH, sMsg, sSh, sRecv, W4, t, slab, gid, tid4);
    l4_chunk<3, 1, 1>(sW, sB, sH, sMsg, sSh, sRecv, W4, t, slab, gid, tid4);
    l4_chunk<5, 4, 2>(sW, sB, sH, sMsg, sSh, sRecv, W4, t, slab, gid, tid4);
}

// ---------------- linear_down ----------------
template <int D, int KOFF, int OFF>
__device__ __forceinline__ void down_part(const float* __restrict__ sAg,
                                          const float* __restrict__ wrow,
                                          float* __restrict__ outn, int dch) {
    float acc[D];
#pragma unroll
    for (int m = 0; m < D; ++m) acc[m] = 0.f;
#pragma unroll
    for (int c4 = 0; c4 < 16; ++c4) {
        float4 w = *(const float4*)(wrow + c4 * 4);
#pragma unroll
        for (int m = 0; m < D; ++m) {
            float4 a = *(const float4*)(sAg + (KOFF + m) * 64 + c4 * 4);
            acc[m] += a.x * w.x + a.y * w.y + a.z * w.z + a.w * w.w;
        }
    }
#pragma unroll
    for (int m = 0; m < D; ++m)
        outn[OFF + dch * D + m] = acc[m] * 0.125f;
}

__global__ __launch_bounds__(256) void k_down(const float* __restrict__ Wd,
                                              float* __restrict__ out) {
    extern __shared__ float smf[];
    float* sWt = smf;                 // [192][68]
    float* sAg = smf + 192 * 68;      // [576]
    int t = threadIdx.x;
    for (int idx = t; idx < 3 * 4096; idx += 256) {
        int l = idx >> 12, rem = idx & 4095, c = rem >> 6, dch = rem & 63;
        sWt[(l * 64 + dch) * 68 + c] = Wd[idx];
    }
    __syncthreads();
    int nb = blockIdx.x * 8;
    for (int i = 0; i < 8; ++i) {
        int n = nb + i;
        for (int idx = t; idx < 576; idx += 256)
            sAg[idx] = g_agg[(size_t)n * 576 + idx];
        __syncthreads();
        if (t < 192) {
            int l = t >> 6, dch = t & 63;
            float* outn = out + (size_t)n * 576;
            const float* wrow = sWt + t * 68;
            if (l == 0)      down_part<1, 0, 0>(sAg, wrow, outn, dch);
            else if (l == 1) down_part<3, 1, 64>(sAg, wrow, outn, dch);
            else             down_part<5, 4, 256>(sAg, wrow, outn, dch);
        }
        __syncthreads();
    }
}

// ---------------- launch ----------------
extern "C" void kernel_launch(void* const* d_in, const int* in_sizes, int n_in,
                              void* d_out, int out_size) {
    const float* evec = (const float*)d_in[0];
    const float* nf   = (const float*)d_in[1];
    const float* rad  = (const float*)d_in[2];
    const int* senders   = (const int*)d_in[3];
    const int* receivers = (const int*)d_in[4];
    const float* Wup = (const float*)d_in[5];
    const float* W1  = (const float*)d_in[6];
    const float* W2  = (const float*)d_in[7];
    const float* W3  = (const float*)d_in[8];
    const float* W4  = (const float*)d_in[9];
    const float* Wd  = (const float*)d_in[10];
    float* out = (float*)d_out;

    const int SMEM_EDGE = SMEM_EDGE_WORDS * 4;            // 169472 B
    const int SMEM_DOWN = (192 * 68 + 9 * 64) * 4;        // 54528 B
    cudaFuncSetAttribute(k_edge, cudaFuncAttributeMaxDynamicSharedMemorySize, SMEM_EDGE);
    cudaFuncSetAttribute(k_down, cudaFuncAttributeMaxDynamicSharedMemorySize, SMEM_DOWN);

    k_zero<<<(N_NODES + 255) / 256, 256>>>();
    k_zeroagg<<<(N_NODES * 9 * 64 / 4 + 255) / 256, 256>>>();
    k_count<<<N_EDGES / 256, 256>>>(receivers);
    k_scan<<<1, 256>>>();
    k_fill<<<N_EDGES / 256, 256>>>(receivers, senders);
    k_h<<<N_NODES / 4, 256>>>(nf, Wup);
    k_edge<<<N_EDGES / TE, 256, SMEM_EDGE>>>(evec, rad, W1, W2, W3, W4);
    k_down<<<N_NODES / 8, 256, SMEM_DOWN>>>(Wd, out);
}

// round 4
// speedup vs baseline: 1.3048x; 1.3048x over previous
#include <cuda_runtime.h>
#include <cstdint>

#define N_NODES 10000
#define N_EDGES 320000
#define CH 64
#define TE 128          // edges (CSR positions) per block in fused edge kernel
#define AP 76           // activation smem pitch (conflict-free A-frag loads)
#define WP 68           // weight smem pitch (conflict-free B-frag loads)

// ---------------- scratch (device globals; allocation-free) ----------------
__device__ float g_h[N_NODES * CH];                 // 2.56 MB
__device__ float g_agg[(size_t)N_NODES * 9 * 64];   // 23 MB: [n][k][c]; zeroed by k_down after read
__device__ int   g_count[N_NODES];                  // zeroed by k_scan after read
__device__ int   g_rowstart[N_NODES + 1];
__device__ int   g_cursor[N_NODES];
__device__ int   g_csr[N_EDGES];                    // pos -> edge id
__device__ int   g_send[N_EDGES];                   // pos -> sender node
__device__ int   g_recv[N_EDGES];                   // pos -> receiver node

__device__ __forceinline__ float silu_f(float x) {
    return x / (1.f + __expf(-x));
}

__device__ __forceinline__ uint32_t f2tf32(float f) {
    uint32_t r;
    asm("cvt.rna.tf32.f32 %0, %1;" : "=r"(r) : "f"(f));
    return r;
}

__device__ __forceinline__ void mma_tf32(float acc[4], uint32_t a0, uint32_t a1,
                                         uint32_t a2, uint32_t a3,
                                         uint32_t b0, uint32_t b1) {
    asm volatile(
        "mma.sync.aligned.m16n8k8.row.col.f32.tf32.tf32.f32 "
        "{%0,%1,%2,%3}, {%4,%5,%6,%7}, {%8,%9}, {%0,%1,%2,%3};\n"
        : "+f"(acc[0]), "+f"(acc[1]), "+f"(acc[2]), "+f"(acc[3])
        : "r"(a0), "r"(a1), "r"(a2), "r"(a3), "r"(b0), "r"(b1));
}

// ---------------- launch 1: edge count histogram + h = (nf @ W_up)/8 ----------------
__global__ __launch_bounds__(256) void k_count_h(const int* __restrict__ recv,
                                                 const float* __restrict__ nf,
                                                 const float* __restrict__ Wup) {
    __shared__ float sW[64 * 64];
    __shared__ float sN[8 * 64];
    int t = threadIdx.x;
    int e = blockIdx.x * 256 + t;
    atomicAdd(&g_count[recv[e]], 1);          // N_EDGES % 256 == 0

    for (int idx = t; idx < 1024; idx += 256)
        ((float4*)sW)[idx] = ((const float4*)Wup)[idx];
    int n0 = blockIdx.x * 8;                  // 1250 * 8 = 10000
    if (t < 128)
        ((float4*)sN)[t] = ((const float4*)(nf + (size_t)n0 * 64))[t];
    __syncthreads();

#pragma unroll
    for (int j = 0; j < 2; ++j) {
        int o = t + j * 256;
        int row = o >> 6, c = o & 63;
        float a0 = 0.f, a1 = 0.f;
#pragma unroll
        for (int k = 0; k < 64; k += 2) {
            a0 = fmaf(sN[row * 64 + k],     sW[k * 64 + c],       a0);
            a1 = fmaf(sN[row * 64 + k + 1], sW[(k + 1) * 64 + c], a1);
        }
        g_h[(size_t)(n0 + row) * 64 + c] = (a0 + a1) * 0.125f;
    }
}

// ---------------- launch 2: parallel exclusive scan (+ zero g_count) ----------------
__global__ __launch_bounds__(1024) void k_scan() {
    __shared__ int warpsum[32];
    int t = threadIdx.x, lane = t & 31, w = t >> 5;
    int base = t * 10;
    int c[10];
    int s = 0;
#pragma unroll
    for (int i = 0; i < 10; ++i) {
        int idx = base + i;
        c[i] = (idx < N_NODES) ? g_count[idx] : 0;
        s += c[i];
    }
    int pre = s;
#pragma unroll
    for (int d = 1; d < 32; d <<= 1) {
        int v = __shfl_up_sync(0xffffffffu, pre, d);
        if (lane >= d) pre += v;
    }
    if (lane == 31) warpsum[w] = pre;
    __syncthreads();
    if (w == 0) {
        int v = warpsum[lane];
#pragma unroll
        for (int d = 1; d < 32; d <<= 1) {
            int u = __shfl_up_sync(0xffffffffu, v, d);
            if (lane >= d) v += u;
        }
        warpsum[lane] = v;
    }
    __syncthreads();
    int wbase = (w > 0) ? warpsum[w - 1] : 0;
    int run = wbase + pre - s;                // exclusive prefix
#pragma unroll
    for (int i = 0; i < 10; ++i) {
        int idx = base + i;
        if (idx < N_NODES) {
            g_rowstart[idx] = run;
            g_cursor[idx] = run;
            run += c[i];
            g_count[idx] = 0;                 // restore invariant for next call
        }
    }
    if (t == 1023) g_rowstart[N_NODES] = warpsum[31];
}

// ---------------- launch 3: CSR fill ----------------
__global__ void k_fill(const int* __restrict__ recv, const int* __restrict__ send) {
    int e = blockIdx.x * blockDim.x + threadIdx.x;
    if (e < N_EDGES) {
        int r = recv[e];
        int pos = atomicAdd(&g_cursor[r], 1);
        g_csr[pos] = e;
        g_send[pos] = send[e];
        g_recv[pos] = r;
    }
}

// ---------------- launch 4 (profiled): fused MLP + SH + TP + segment scatter ----------------
// smem word offsets
#define O_ACT   0                 // [128][AP] tf32 activations (in-place across layers)
#define O_U     9728              // union: sW [64][WP]=4352w  /  sMsg [128][66]=8448w
#define O_H     18176             // h tile [128][66] floats
#define O_SSH   26624             // sh [128][12] floats
#define O_RECV  28160             // recv ids [128]
#define SMEM_EDGE_WORDS 28288     // 113152 B -> 2 CTAs/SM

__device__ __forceinline__ void load_w64(uint32_t* __restrict__ sW,
                                         const float* __restrict__ gW, int t) {
    for (int idx = t; idx < 4096; idx += 256) {
        int k = idx >> 6, n = idx & 63;
        sW[n * WP + k] = f2tf32(gW[idx]);
    }
}

template <int KSTEPS>
__device__ __forceinline__ void mma_layer(const uint32_t* __restrict__ sIn,
                                          const uint32_t* __restrict__ sW,
                                          float acc[8][4],
                                          int slab, int gid, int tid4) {
#pragma unroll
    for (int nt = 0; nt < 8; ++nt) {
        acc[nt][0] = 0.f; acc[nt][1] = 0.f; acc[nt][2] = 0.f; acc[nt][3] = 0.f;
    }
#pragma unroll
    for (int kk = 0; kk < KSTEPS; ++kk) {
        int c0 = kk * 8 + tid4;
        uint32_t a0 = sIn[(slab + gid) * AP + c0];
        uint32_t a1 = sIn[(slab + gid + 8) * AP + c0];
        uint32_t a2 = sIn[(slab + gid) * AP + c0 + 4];
        uint32_t a3 = sIn[(slab + gid + 8) * AP + c0 + 4];
#pragma unroll
        for (int nt = 0; nt < 8; ++nt) {
            uint32_t b0 = sW[(nt * 8 + gid) * WP + c0];
            uint32_t b1 = sW[(nt * 8 + gid) * WP + c0 + 4];
            mma_tf32(acc[nt], a0, a1, a2, a3, b0, b1);
        }
    }
}

// in-place store is safe: rows [slab, slab+16) are warp-private for both the
// A-fragment reads and these writes, and the final mma.sync of the layer is a
// warp-wide convergence point, so all lanes' LDS reads precede any lane's STS.
__device__ __forceinline__ void store_act_mma(uint32_t* __restrict__ sOut,
                                              float acc[8][4], float scale,
                                              int slab, int gid, int tid4) {
#pragma unroll
    for (int nt = 0; nt < 8; ++nt) {
        int col = nt * 8 + 2 * tid4;
        uint32_t t0 = f2tf32(silu_f(acc[nt][0] * scale));
        uint32_t t1 = f2tf32(silu_f(acc[nt][1] * scale));
        uint32_t t2 = f2tf32(silu_f(acc[nt][2] * scale));
        uint32_t t3 = f2tf32(silu_f(acc[nt][3] * scale));
        *(uint2*)(sOut + (slab + gid) * AP + col)     = make_uint2(t0, t1);
        *(uint2*)(sOut + (slab + gid + 8) * AP + col) = make_uint2(t2, t3);
    }
}

template <int D, int KOFF, int CHK>
__device__ __forceinline__ void l4_chunk(uint32_t* __restrict__ sU,
                                         const uint32_t* __restrict__ sAct,
                                         const float* __restrict__ sH,
                                         const float* __restrict__ sSh,
                                         const int* __restrict__ sRecv,
                                         const float* __restrict__ W4,
                                         int t, int slab, int gid, int tid4) {
    // load W4 chunk (cols [CHK*64, CHK*64+64)), transposed, into union region
    for (int idx = t; idx < 4096; idx += 256) {
        int k = idx >> 6, n = idx & 63;
        sU[n * WP + k] = f2tf32(W4[(size_t)k * 192 + CHK * 64 + n]);
    }
    __syncthreads();

    float acc[8][4];
    mma_layer<8>(sAct, sU, acc, slab, gid, tid4);
    __syncthreads();                     // all warps done reading sU as weights

    // msg = acc * h * (1/sqrt(64) / avg_neigh) staged into union region
    float* sMsg = (float*)sU;
    const float S = 1.f / 256.f;
#pragma unroll
    for (int nt = 0; nt < 8; ++nt) {
        int col = nt * 8 + 2 * tid4;
        int r0 = slab + gid, r1 = r0 + 8;
        float2 h0 = *(const float2*)(sH + r0 * 66 + col);
        float2 h1 = *(const float2*)(sH + r1 * 66 + col);
        *(float2*)(sMsg + r0 * 66 + col) =
            make_float2(acc[nt][0] * h0.x * S, acc[nt][1] * h0.y * S);
        *(float2*)(sMsg + r1 * 66 + col) =
            make_float2(acc[nt][2] * h1.x * S, acc[nt][3] * h1.y * S);
    }
    __syncthreads();

    // segment reduction over rows; atomic flush per receiver run
    {
        int c = t & 63, q = t >> 6;
        int rbase = q * 32;
        int ncur = sRecv[rbase];
        float a[D];
#pragma unroll
        for (int k = 0; k < D; ++k) a[k] = 0.f;
        for (int r = 0; r < 32; ++r) {
            int row = rbase + r;
            int n = sRecv[row];
            if (n != ncur) {
#pragma unroll
                for (int k = 0; k < D; ++k) {
                    atomicAdd(&g_agg[(size_t)(ncur * 9 + KOFF + k) * 64 + c], a[k]);
                    a[k] = 0.f;
                }
                ncur = n;
            }
            float m = sMsg[row * 66 + c];
#pragma unroll
            for (int k = 0; k < D; ++k)
                a[k] = fmaf(m, sSh[row * 12 + KOFF + k], a[k]);
        }
#pragma unroll
        for (int k = 0; k < D; ++k)
            atomicAdd(&g_agg[(size_t)(ncur * 9 + KOFF + k) * 64 + c], a[k]);
    }
    __syncthreads();                     // before next chunk's W4 load reuses sU
}

__global__ __launch_bounds__(256) void k_edge(const float* __restrict__ evec,
                                              const float* __restrict__ rad,
                                              const float* __restrict__ W1,
                                              const float* __restrict__ W2,
                                              const float* __restrict__ W3,
                                              const float* __restrict__ W4) {
    extern __shared__ uint32_t sm[];
    uint32_t* sAct = sm + O_ACT;
    uint32_t* sU   = sm + O_U;
    float* sH      = (float*)(sm + O_H);
    float* sSh     = (float*)(sm + O_SSH);
    int*   sRecv   = (int*)(sm + O_RECV);

    int t = threadIdx.x;
    int lane = t & 31, warp = t >> 5;
    int gid = lane >> 2, tid4 = lane & 3, slab = warp * 16;
    int pos_base = blockIdx.x * TE;

    // per-position: SH + radial + recv (CSR order)
    if (t < TE) {
        int pos = pos_base + t;
        int e = g_csr[pos];
        sRecv[t] = g_recv[pos];

        float x = evec[(size_t)e * 3], y = evec[(size_t)e * 3 + 1],
              z = evec[(size_t)e * 3 + 2];
        float rn = rsqrtf(x * x + y * y + z * z);
        x *= rn; y *= rn; z *= rn;
        const float c3  = 1.7320508075688772f;
        const float c15 = 3.872983346207417f;
        const float c5h = 1.118033988749895f;
        const float c15h= 1.9364916731037085f;
        float* o = sSh + t * 12;
        o[0] = 1.f;
        o[1] = c3 * x; o[2] = c3 * y; o[3] = c3 * z;
        o[4] = c15 * x * y; o[5] = c15 * y * z;
        o[6] = c5h * (3.f * z * z - 1.f);
        o[7] = c15 * x * z; o[8] = c15h * (x * x - y * y);

        float4 r0 = *(const float4*)(rad + (size_t)e * 8);
        float4 r1 = *(const float4*)(rad + (size_t)e * 8 + 4);
        uint32_t* dst = sAct + t * AP;
        dst[0] = f2tf32(r0.x); dst[1] = f2tf32(r0.y);
        dst[2] = f2tf32(r0.z); dst[3] = f2tf32(r0.w);
        dst[4] = f2tf32(r1.x); dst[5] = f2tf32(r1.y);
        dst[6] = f2tf32(r1.z); dst[7] = f2tf32(r1.w);
    }
    // h tile: gather rows of g_h for this block's senders
    for (int idx = t; idx < 128 * 32; idx += 256) {
        int row = idx >> 5, c2 = idx & 31;
        int s = g_send[pos_base + row];
        *(float2*)(sH + row * 66 + c2 * 2) =
            *(const float2*)(g_h + (size_t)s * 64 + c2 * 2);
    }
    // W1: [8][64] -> sU[n][k]
    for (int idx = t; idx < 512; idx += 256) {
        int k = idx >> 6, n = idx & 63;
        sU[n * WP + k] = f2tf32(W1[idx]);
    }
    __syncthreads();

    float acc[8][4];

    // L1: [128,8] @ [8,64], in place
    mma_layer<1>(sAct, sU, acc, slab, gid, tid4);
    store_act_mma(sAct, acc, 0.35355339059327373f, slab, gid, tid4);
    __syncthreads();

    // L2, in place
    load_w64(sU, W2, t);
    __syncthreads();
    mma_layer<8>(sAct, sU, acc, slab, gid, tid4);
    store_act_mma(sAct, acc, 0.125f, slab, gid, tid4);
    __syncthreads();

    // L3, in place
    load_w64(sU, W3, t);
    __syncthreads();
    mma_layer<8>(sAct, sU, acc, slab, gid, tid4);
    store_act_mma(sAct, acc, 0.125f, slab, gid, tid4);
    __syncthreads();

    // L4 + tensor product + segment scatter, one l at a time
    l4_chunk<1, 0, 0>(sU, sAct, sH, sSh, sRecv, W4, t, slab, gid, tid4);
    l4_chunk<3, 1, 1>(sU, sAct, sH, sSh, sRecv, W4, t, slab, gid, tid4);
    l4_chunk<5, 4, 2>(sU, sAct, sH, sSh, sRecv, W4, t, slab, gid, tid4);
}

// ---------------- launch 5: linear_down (also re-zeroes g_agg) ----------------
template <int D, int KOFF, int OFF>
__device__ __forceinline__ void down_part(const float* __restrict__ sAg,
                                          const float* __restrict__ wrow,
                                          float* __restrict__ outn, int dch) {
    float acc[D];
#pragma unroll
    for (int m = 0; m < D; ++m) acc[m] = 0.f;
#pragma unroll
    for (int c4 = 0; c4 < 16; ++c4) {
        float4 w = *(const float4*)(wrow + c4 * 4);
#pragma unroll
        for (int m = 0; m < D; ++m) {
            float4 a = *(const float4*)(sAg + (KOFF + m) * 64 + c4 * 4);
            acc[m] += a.x * w.x + a.y * w.y + a.z * w.z + a.w * w.w;
        }
    }
#pragma unroll
    for (int m = 0; m < D; ++m)
        outn[OFF + dch * D + m] = acc[m] * 0.125f;
}

__global__ __launch_bounds__(256) void k_down(const float* __restrict__ Wd,
                                              float* __restrict__ out) {
    extern __shared__ float smf[];
    float* sWt = smf;                 // [192][68]
    float* sAg = smf + 192 * 68;      // [576]
    int t = threadIdx.x;
    for (int idx = t; idx < 3 * 4096; idx += 256) {
        int l = idx >> 12, rem = idx & 4095, c = rem >> 6, dch = rem & 63;
        sWt[(l * 64 + dch) * 68 + c] = Wd[idx];
    }
    __syncthreads();
    int nb = blockIdx.x * 8;
    for (int i = 0; i < 8; ++i) {
        int n = nb + i;
        for (int idx = t; idx < 576; idx += 256) {
            sAg[idx] = g_agg[(size_t)n * 576 + idx];
            g_agg[(size_t)n * 576 + idx] = 0.f;    // restore invariant
        }
        __syncthreads();
        if (t < 192) {
            int l = t >> 6, dch = t & 63;
            float* outn = out + (size_t)n * 576;
            const float* wrow = sWt + t * 68;
            if (l == 0)      down_part<1, 0, 0>(sAg, wrow, outn, dch);
            else if (l == 1) down_part<3, 1, 64>(sAg, wrow, outn, dch);
            else             down_part<5, 4, 256>(sAg, wrow, outn, dch);
        }
        __syncthreads();
    }
}

// ---------------- launch ----------------
extern "C" void kernel_launch(void* const* d_in, const int* in_sizes, int n_in,
                              void* d_out, int out_size) {
    const float* evec = (const float*)d_in[0];
    const float* nf   = (const float*)d_in[1];
    const float* rad  = (const float*)d_in[2];
    const int* senders   = (const int*)d_in[3];
    const int* receivers = (const int*)d_in[4];
    const float* Wup = (const float*)d_in[5];
    const float* W1  = (const float*)d_in[6];
    const float* W2  = (const float*)d_in[7];
    const float* W3  = (const float*)d_in[8];
    const float* W4  = (const float*)d_in[9];
    const float* Wd  = (const float*)d_in[10];
    float* out = (float*)d_out;

    const int SMEM_EDGE = SMEM_EDGE_WORDS * 4;            // 113152 B -> 2 CTAs/SM
    const int SMEM_DOWN = (192 * 68 + 9 * 64) * 4;        // 54528 B
    cudaFuncSetAttribute(k_edge, cudaFuncAttributeMaxDynamicSharedMemorySize, SMEM_EDGE);
    cudaFuncSetAttribute(k_down, cudaFuncAttributeMaxDynamicSharedMemorySize, SMEM_DOWN);

    k_count_h<<<N_EDGES / 256, 256>>>(receivers, nf, Wup);
    k_scan<<<1, 1024>>>();
    k_fill<<<N_EDGES / 256, 256>>>(receivers, senders);
    k_edge<<<N_EDGES / TE, 256, SMEM_EDGE>>>(evec, rad, W1, W2, W3, W4);
    k_down<<<N_NODES / 8, 256, SMEM_DOWN>>>(Wd, out);
}

// round 5
// speedup vs baseline: 1.5155x; 1.1615x over previous
#include <cuda_runtime.h>
#include <cstdint>

#define N_NODES 10000
#define N_EDGES 320000
#define CH 64
#define TE 64           // edges (CSR positions) per block in fused edge kernel
#define AP 76           // activation smem pitch (conflict-free A-frag loads)
#define WP 68           // weight smem pitch (conflict-free B-frag loads)

// ---------------- scratch (device globals; allocation-free) ----------------
__device__ float g_h[N_NODES * CH];                 // 2.56 MB
__device__ float g_agg[(size_t)N_NODES * 9 * 64];   // 23 MB; zeroed by k_down after read
__device__ int   g_count[N_NODES];                  // zeroed by k_scan after read
__device__ int   g_rowstart[N_NODES + 1];
__device__ int   g_cursor[N_NODES];
__device__ int   g_csr[N_EDGES];                    // pos -> edge id
__device__ int   g_send[N_EDGES];                   // pos -> sender node
__device__ int   g_recv[N_EDGES];                   // pos -> receiver node

__device__ __forceinline__ float silu_f(float x) {
    return x / (1.f + __expf(-x));
}

__device__ __forceinline__ uint32_t f2tf32(float f) {
    uint32_t r;
    asm("cvt.rna.tf32.f32 %0, %1;" : "=r"(r) : "f"(f));
    return r;
}

__device__ __forceinline__ void mma_tf32(float acc[4], uint32_t a0, uint32_t a1,
                                         uint32_t a2, uint32_t a3,
                                         uint32_t b0, uint32_t b1) {
    asm volatile(
        "mma.sync.aligned.m16n8k8.row.col.f32.tf32.tf32.f32 "
        "{%0,%1,%2,%3}, {%4,%5,%6,%7}, {%8,%9}, {%0,%1,%2,%3};\n"
        : "+f"(acc[0]), "+f"(acc[1]), "+f"(acc[2]), "+f"(acc[3])
        : "r"(a0), "r"(a1), "r"(a2), "r"(a3), "r"(b0), "r"(b1));
}

// ---------------- launch 1: edge count histogram + h = (nf @ W_up)/8 ----------------
__global__ __launch_bounds__(256) void k_count_h(const int* __restrict__ recv,
                                                 const float* __restrict__ nf,
                                                 const float* __restrict__ Wup) {
    __shared__ float sW[64 * 64];
    __shared__ float sN[8 * 64];
    int t = threadIdx.x;
    int e = blockIdx.x * 256 + t;
    atomicAdd(&g_count[recv[e]], 1);          // N_EDGES % 256 == 0

    for (int idx = t; idx < 1024; idx += 256)
        ((float4*)sW)[idx] = ((const float4*)Wup)[idx];
    int n0 = blockIdx.x * 8;                  // 1250 * 8 = 10000
    if (t < 128)
        ((float4*)sN)[t] = ((const float4*)(nf + (size_t)n0 * 64))[t];
    __syncthreads();

#pragma unroll
    for (int j = 0; j < 2; ++j) {
        int o = t + j * 256;
        int row = o >> 6, c = o & 63;
        float a0 = 0.f, a1 = 0.f;
#pragma unroll
        for (int k = 0; k < 64; k += 2) {
            a0 = fmaf(sN[row * 64 + k],     sW[k * 64 + c],       a0);
            a1 = fmaf(sN[row * 64 + k + 1], sW[(k + 1) * 64 + c], a1);
        }
        g_h[(size_t)(n0 + row) * 64 + c] = (a0 + a1) * 0.125f;
    }
}

// ---------------- launch 2: parallel exclusive scan (+ zero g_count) ----------------
__global__ __launch_bounds__(1024) void k_scan() {
    __shared__ int warpsum[32];
    int t = threadIdx.x, lane = t & 31, w = t >> 5;
    int base = t * 10;
    int c[10];
    int s = 0;
#pragma unroll
    for (int i = 0; i < 10; ++i) {
        int idx = base + i;
        c[i] = (idx < N_NODES) ? g_count[idx] : 0;
        s += c[i];
    }
    int pre = s;
#pragma unroll
    for (int d = 1; d < 32; d <<= 1) {
        int v = __shfl_up_sync(0xffffffffu, pre, d);
        if (lane >= d) pre += v;
    }
    if (lane == 31) warpsum[w] = pre;
    __syncthreads();
    if (w == 0) {
        int v = warpsum[lane];
#pragma unroll
        for (int d = 1; d < 32; d <<= 1) {
            int u = __shfl_up_sync(0xffffffffu, v, d);
            if (lane >= d) v += u;
        }
        warpsum[lane] = v;
    }
    __syncthreads();
    int wbase = (w > 0) ? warpsum[w - 1] : 0;
    int run = wbase + pre - s;                // exclusive prefix
#pragma unroll
    for (int i = 0; i < 10; ++i) {
        int idx = base + i;
        if (idx < N_NODES) {
            g_rowstart[idx] = run;
            g_cursor[idx] = run;
            run += c[i];
            g_count[idx] = 0;                 // restore invariant for next call
        }
    }
    if (t == 1023) g_rowstart[N_NODES] = warpsum[31];
}

// ---------------- launch 3: CSR fill ----------------
__global__ void k_fill(const int* __restrict__ recv, const int* __restrict__ send) {
    int e = blockIdx.x * blockDim.x + threadIdx.x;
    if (e < N_EDGES) {
        int r = recv[e];
        int pos = atomicAdd(&g_cursor[r], 1);
        g_csr[pos] = e;
        g_send[pos] = send[e];
        g_recv[pos] = r;
    }
}

// ---------------- launch 4 (profiled): fused MLP + SH + TP + segment scatter ----------------
// 64 edges/block, 256 threads = 8 warps. Warp w: rows [(w>>1)*16, +16), N-half (w&1).
// smem word offsets (total 14272 words = 57088 B -> 4 CTAs/SM)
#define O_ACT   0                 // [64][AP] tf32 activations (in-place across layers)
#define O_U     4864              // union: sW [64][WP]=4352w  /  sMsg [64][66]=4224w
#define O_H     9216              // h tile [64][66] floats
#define O_SSH   13440             // sh [64][12] floats
#define O_RECV  14208             // recv ids [64]
#define SMEM_EDGE_WORDS 14272

__device__ __forceinline__ void load_w64(uint32_t* __restrict__ sW,
                                         const float* __restrict__ gW, int t) {
    for (int idx = t; idx < 4096; idx += 256) {
        int k = idx >> 6, n = idx & 63;
        sW[n * WP + k] = f2tf32(gW[idx]);
    }
}

// Warp computes rows [slab, slab+16) x cols [hbase, hbase+32) of the layer output.
template <int KSTEPS>
__device__ __forceinline__ void mma_layer(const uint32_t* __restrict__ sIn,
                                          const uint32_t* __restrict__ sW,
                                          float acc[4][4],
                                          int slab, int hbase, int gid, int tid4) {
#pragma unroll
    for (int nt = 0; nt < 4; ++nt) {
        acc[nt][0] = 0.f; acc[nt][1] = 0.f; acc[nt][2] = 0.f; acc[nt][3] = 0.f;
    }
#pragma unroll
    for (int kk = 0; kk < KSTEPS; ++kk) {
        int c0 = kk * 8 + tid4;
        uint32_t a0 = sIn[(slab + gid) * AP + c0];
        uint32_t a1 = sIn[(slab + gid + 8) * AP + c0];
        uint32_t a2 = sIn[(slab + gid) * AP + c0 + 4];
        uint32_t a3 = sIn[(slab + gid + 8) * AP + c0 + 4];
#pragma unroll
        for (int nt = 0; nt < 4; ++nt) {
            int n = hbase + nt * 8 + gid;
            uint32_t b0 = sW[n * WP + c0];
            uint32_t b1 = sW[n * WP + c0 + 4];
            mma_tf32(acc[nt], a0, a1, a2, a3, b0, b1);
        }
    }
}

// In-place store: rows are warp-pair-shared only across the block-wide sync that
// always follows before the next layer reads.
__device__ __forceinline__ void store_act_mma(uint32_t* __restrict__ sOut,
                                              float acc[4][4], float scale,
                                              int slab, int hbase, int gid, int tid4) {
#pragma unroll
    for (int nt = 0; nt < 4; ++nt) {
        int col = hbase + nt * 8 + 2 * tid4;
        uint32_t t0 = f2tf32(silu_f(acc[nt][0] * scale));
        uint32_t t1 = f2tf32(silu_f(acc[nt][1] * scale));
        uint32_t t2 = f2tf32(silu_f(acc[nt][2] * scale));
        uint32_t t3 = f2tf32(silu_f(acc[nt][3] * scale));
        *(uint2*)(sOut + (slab + gid) * AP + col)     = make_uint2(t0, t1);
        *(uint2*)(sOut + (slab + gid + 8) * AP + col) = make_uint2(t2, t3);
    }
}

template <int D, int KOFF, int CHK>
__device__ __forceinline__ void l4_chunk(uint32_t* __restrict__ sU,
                                         const uint32_t* __restrict__ sAct,
                                         const float* __restrict__ sH,
                                         const float* __restrict__ sSh,
                                         const int* __restrict__ sRecv,
                                         const float* __restrict__ W4,
                                         int t, int slab, int hbase, int gid, int tid4) {
    // load W4 chunk (cols [CHK*64, CHK*64+64)), transposed, into union region
    for (int idx = t; idx < 4096; idx += 256) {
        int k = idx >> 6, n = idx & 63;
        sU[n * WP + k] = f2tf32(W4[(size_t)k * 192 + CHK * 64 + n]);
    }
    __syncthreads();

    float acc[4][4];
    mma_layer<8>(sAct, sU, acc, slab, hbase, gid, tid4);
    __syncthreads();                     // all warps done reading sU as weights

    // msg = acc * h * (1/sqrt(64) / avg_neigh) staged into union region
    float* sMsg = (float*)sU;
    const float S = 1.f / 256.f;
#pragma unroll
    for (int nt = 0; nt < 4; ++nt) {
        int col = hbase + nt * 8 + 2 * tid4;
        int r0 = slab + gid, r1 = r0 + 8;
        float2 h0 = *(const float2*)(sH + r0 * 66 + col);
        float2 h1 = *(const float2*)(sH + r1 * 66 + col);
        *(float2*)(sMsg + r0 * 66 + col) =
            make_float2(acc[nt][0] * h0.x * S, acc[nt][1] * h0.y * S);
        *(float2*)(sMsg + r1 * 66 + col) =
            make_float2(acc[nt][2] * h1.x * S, acc[nt][3] * h1.y * S);
    }
    __syncthreads();

    // segment reduction over rows; atomic flush per receiver run
    {
        int c = t & 63, q = t >> 6;
        int rbase = q * 16;
        int ncur = sRecv[rbase];
        float a[D];
#pragma unroll
        for (int k = 0; k < D; ++k) a[k] = 0.f;
#pragma unroll 4
        for (int r = 0; r < 16; ++r) {
            int row = rbase + r;
            int n = sRecv[row];
            if (n != ncur) {
#pragma unroll
                for (int k = 0; k < D; ++k) {
                    atomicAdd(&g_agg[(size_t)(ncur * 9 + KOFF + k) * 64 + c], a[k]);
                    a[k] = 0.f;
                }
                ncur = n;
            }
            float m = sMsg[row * 66 + c];
#pragma unroll
            for (int k = 0; k < D; ++k)
                a[k] = fmaf(m, sSh[row * 12 + KOFF + k], a[k]);
        }
#pragma unroll
        for (int k = 0; k < D; ++k)
            atomicAdd(&g_agg[(size_t)(ncur * 9 + KOFF + k) * 64 + c], a[k]);
    }
    __syncthreads();                     // before next chunk's W4 load reuses sU
}

__global__ __launch_bounds__(256) void k_edge(const float* __restrict__ evec,
                                              const float* __restrict__ rad,
                                              const float* __restrict__ W1,
                                              const float* __restrict__ W2,
                                              const float* __restrict__ W3,
                                              const float* __restrict__ W4) {
    extern __shared__ uint32_t sm[];
    uint32_t* sAct = sm + O_ACT;
    uint32_t* sU   = sm + O_U;
    float* sH      = (float*)(sm + O_H);
    float* sSh     = (float*)(sm + O_SSH);
    int*   sRecv   = (int*)(sm + O_RECV);

    int t = threadIdx.x;
    int lane = t & 31, warp = t >> 5;
    int gid = lane >> 2, tid4 = lane & 3;
    int slab = (warp >> 1) * 16, hbase = (warp & 1) * 32;
    int pos_base = blockIdx.x * TE;

    // per-position: SH + radial + recv (CSR order)
    if (t < TE) {
        int pos = pos_base + t;
        int e = g_csr[pos];
        sRecv[t] = g_recv[pos];

        float x = evec[(size_t)e * 3], y = evec[(size_t)e * 3 + 1],
              z = evec[(size_t)e * 3 + 2];
        float rn = rsqrtf(x * x + y * y + z * z);
        x *= rn; y *= rn; z *= rn;
        const float c3  = 1.7320508075688772f;
        const float c15 = 3.872983346207417f;
        const float c5h = 1.118033988749895f;
        const float c15h= 1.9364916731037085f;
        float* o = sSh + t * 12;
        o[0] = 1.f;
        o[1] = c3 * x; o[2] = c3 * y; o[3] = c3 * z;
        o[4] = c15 * x * y; o[5] = c15 * y * z;
        o[6] = c5h * (3.f * z * z - 1.f);
        o[7] = c15 * x * z; o[8] = c15h * (x * x - y * y);

        float4 r0 = *(const float4*)(rad + (size_t)e * 8);
        float4 r1 = *(const float4*)(rad + (size_t)e * 8 + 4);
        uint32_t* dst = sAct + t * AP;
        dst[0] = f2tf32(r0.x); dst[1] = f2tf32(r0.y);
        dst[2] = f2tf32(r0.z); dst[3] = f2tf32(r0.w);
        dst[4] = f2tf32(r1.x); dst[5] = f2tf32(r1.y);
        dst[6] = f2tf32(r1.z); dst[7] = f2tf32(r1.w);
    }
    // h tile: gather rows of g_h for this block's senders
    for (int idx = t; idx < 64 * 32; idx += 256) {
        int row = idx >> 5, c2 = idx & 31;
        int s = g_send[pos_base + row];
        *(float2*)(sH + row * 66 + c2 * 2) =
            *(const float2*)(g_h + (size_t)s * 64 + c2 * 2);
    }
    // W1: [8][64] -> sU[n][k]
    for (int idx = t; idx < 512; idx += 256) {
        int k = idx >> 6, n = idx & 63;
        sU[n * WP + k] = f2tf32(W1[idx]);
    }
    __syncthreads();

    float acc[4][4];

    // L1: [64,8] @ [8,64], in place
    mma_layer<1>(sAct, sU, acc, slab, hbase, gid, tid4);
    store_act_mma(sAct, acc, 0.35355339059327373f, slab, hbase, gid, tid4);
    __syncthreads();

    // L2, in place
    load_w64(sU, W2, t);
    __syncthreads();
    mma_layer<8>(sAct, sU, acc, slab, hbase, gid, tid4);
    store_act_mma(sAct, acc, 0.125f, slab, hbase, gid, tid4);
    __syncthreads();

    // L3, in place
    load_w64(sU, W3, t);
    __syncthreads();
    mma_layer<8>(sAct, sU, acc, slab, hbase, gid, tid4);
    store_act_mma(sAct, acc, 0.125f, slab, hbase, gid, tid4);
    __syncthreads();

    // L4 + tensor product + segment scatter, one l at a time
    l4_chunk<1, 0, 0>(sU, sAct, sH, sSh, sRecv, W4, t, slab, hbase, gid, tid4);
    l4_chunk<3, 1, 1>(sU, sAct, sH, sSh, sRecv, W4, t, slab, hbase, gid, tid4);
    l4_chunk<5, 4, 2>(sU, sAct, sH, sSh, sRecv, W4, t, slab, hbase, gid, tid4);
}

// ---------------- launch 5: linear_down (also re-zeroes g_agg) ----------------
template <int D, int KOFF, int OFF>
__device__ __forceinline__ void down_part(const float* __restrict__ sAg,
                                          const float* __restrict__ wrow,
                                          float* __restrict__ outn, int dch) {
    float acc[D];
#pragma unroll
    for (int m = 0; m < D; ++m) acc[m] = 0.f;
#pragma unroll
    for (int c4 = 0; c4 < 16; ++c4) {
        float4 w = *(const float4*)(wrow + c4 * 4);
#pragma unroll
        for (int m = 0; m < D; ++m) {
            float4 a = *(const float4*)(sAg + (KOFF + m) * 64 + c4 * 4);
            acc[m] += a.x * w.x + a.y * w.y + a.z * w.z + a.w * w.w;
        }
    }
#pragma unroll
    for (int m = 0; m < D; ++m)
        outn[OFF + dch * D + m] = acc[m] * 0.125f;
}

__global__ __launch_bounds__(256) void k_down(const float* __restrict__ Wd,
                                              float* __restrict__ out) {
    extern __shared__ float smf[];
    float* sWt = smf;                 // [192][68]
    float* sAg = smf + 192 * 68;      // [576]
    int t = threadIdx.x;
    for (int idx = t; idx < 3 * 4096; idx += 256) {
        int l = idx >> 12, rem = idx & 4095, c = rem >> 6, dch = rem & 63;
        sWt[(l * 64 + dch) * 68 + c] = Wd[idx];
    }
    __syncthreads();
    int nb = blockIdx.x * 8;
    for (int i = 0; i < 8; ++i) {
        int n = nb + i;
        for (int idx = t; idx < 576; idx += 256) {
            sAg[idx] = g_agg[(size_t)n * 576 + idx];
            g_agg[(size_t)n * 576 + idx] = 0.f;    // restore invariant
        }
        __syncthreads();
        if (t < 192) {
            int l = t >> 6, dch = t & 63;
            float* outn = out + (size_t)n * 576;
            const float* wrow = sWt + t * 68;
            if (l == 0)      down_part<1, 0, 0>(sAg, wrow, outn, dch);
            else if (l == 1) down_part<3, 1, 64>(sAg, wrow, outn, dch);
            else             down_part<5, 4, 256>(sAg, wrow, outn, dch);
        }
        __syncthreads();
    }
}

// ---------------- launch ----------------
extern "C" void kernel_launch(void* const* d_in, const int* in_sizes, int n_in,
                              void* d_out, int out_size) {
    const float* evec = (const float*)d_in[0];
    const float* nf   = (const float*)d_in[1];
    const float* rad  = (const float*)d_in[2];
    const int* senders   = (const int*)d_in[3];
    const int* receivers = (const int*)d_in[4];
    const float* Wup = (const float*)d_in[5];
    const float* W1  = (const float*)d_in[6];
    const float* W2  = (const float*)d_in[7];
    const float* W3  = (const float*)d_in[8];
    const float* W4  = (const float*)d_in[9];
    const float* Wd  = (const float*)d_in[10];
    float* out = (float*)d_out;

    const int SMEM_EDGE = SMEM_EDGE_WORDS * 4;            // 57088 B -> 4 CTAs/SM
    const int SMEM_DOWN = (192 * 68 + 9 * 64) * 4;        // 54528 B
    cudaFuncSetAttribute(k_edge, cudaFuncAttributeMaxDynamicSharedMemorySize, SMEM_EDGE);
    cudaFuncSetAttribute(k_down, cudaFuncAttributeMaxDynamicSharedMemorySize, SMEM_DOWN);

    k_count_h<<<N_EDGES / 256, 256>>>(receivers, nf, Wup);
    k_scan<<<1, 1024>>>();
    k_fill<<<N_EDGES / 256, 256>>>(receivers, senders);
    k_edge<<<N_EDGES / TE, 256, SMEM_EDGE>>>(evec, rad, W1, W2, W3, W4);
    k_down<<<N_NODES / 8, 256, SMEM_DOWN>>>(Wd, out);
}

// round 6
// speedup vs baseline: 2.2597x; 1.4910x over previous
#include <cuda_runtime.h>
#include <cstdint>

#define N_NODES 10000
#define N_EDGES 320000
#define TE 128          // edges per block in fused edge kernel
#define AP 76           // activation smem pitch (conflict-free A-frag loads)

// ---------------- scratch (device globals; allocation-free) ----------------
__device__ float g_h[N_NODES * 64];                 // 2.56 MB
__device__ float g_agg[(size_t)N_NODES * 576];      // 23 MB; zeroed by k_down after read
__device__ int   g_count[N_NODES];                  // zeroed by k_scan after read
__device__ int   g_rowstart[N_NODES + 1];
__device__ int   g_cursor[N_NODES];
__device__ int   g_csr[N_EDGES];
__device__ int   g_send[N_EDGES];
__device__ int   g_recv[N_EDGES];
__device__ uint2 g_wfrag[10496];                    // fragment-ordered tf32 weights (84KB)

// uint2 offsets into g_wfrag
#define U_W1 0
#define U_W2 256
#define U_W3 2304
#define U_W4 4352       // + chunk*2048

__device__ __forceinline__ float silu_f(float x) {
    return x / (1.f + __expf(-x));
}

__device__ __forceinline__ uint32_t f2tf32(float f) {
    uint32_t r;
    asm("cvt.rna.tf32.f32 %0, %1;" : "=r"(r) : "f"(f));
    return r;
}

__device__ __forceinline__ void mma_tf32(float acc[4], uint32_t a0, uint32_t a1,
                                         uint32_t a2, uint32_t a3,
                                         uint32_t b0, uint32_t b1) {
    asm volatile(
        "mma.sync.aligned.m16n8k8.row.col.f32.tf32.tf32.f32 "
        "{%0,%1,%2,%3}, {%4,%5,%6,%7}, {%8,%9}, {%0,%1,%2,%3};\n"
        : "+f"(acc[0]), "+f"(acc[1]), "+f"(acc[2]), "+f"(acc[3])
        : "r"(a0), "r"(a1), "r"(a2), "r"(a3), "r"(b0), "r"(b1));
}

// ---------------- launch 0: pre-convert weights into fragment order ----------------
// Entry u: lane = u&31; rest = u>>5; nt = rest&3; rest >>= 2; kk = rest%KK; hb = rest/KK.
// Value: { tf32(W[k0][n]), tf32(W[k0+4][n]) }, n = co + hb*32 + nt*8 + (lane>>2),
//        k0 = kk*8 + (lane&3).
__global__ void k_prep(const float* __restrict__ W1, const float* __restrict__ W2,
                       const float* __restrict__ W3, const float* __restrict__ W4) {
    int u = blockIdx.x * 256 + threadIdx.x;
    if (u >= 10496) return;
    const float* src; int rs, co, KK, local;
    if (u < 256)       { src = W1; rs = 64;  co = 0;   KK = 1; local = u; }
    else if (u < 2304) { src = W2; rs = 64;  co = 0;   KK = 8; local = u - 256; }
    else if (u < 4352) { src = W3; rs = 64;  co = 0;   KK = 8; local = u - 2304; }
    else if (u < 6400) { src = W4; rs = 192; co = 0;   KK = 8; local = u - 4352; }
    else if (u < 8448) { src = W4; rs = 192; co = 64;  KK = 8; local = u - 6400; }
    else               { src = W4; rs = 192; co = 128; KK = 8; local = u - 8448; }
    int lane = local & 31; int rest = local >> 5;
    int nt = rest & 3; rest >>= 2;
    int kk = rest % KK; int hb = rest / KK;
    int n = co + hb * 32 + nt * 8 + (lane >> 2);
    int k0 = kk * 8 + (lane & 3);
    g_wfrag[u] = make_uint2(f2tf32(src[(size_t)k0 * rs + n]),
                            f2tf32(src[(size_t)(k0 + 4) * rs + n]));
}

// ---------------- launch 1: edge count histogram + h = (nf @ W_up)/8 ----------------
__global__ __launch_bounds__(256) void k_count_h(const int* __restrict__ recv,
                                                 const float* __restrict__ nf,
                                                 const float* __restrict__ Wup) {
    __shared__ float sW[64 * 64];
    __shared__ float sN[8 * 64];
    int t = threadIdx.x;
    int e = blockIdx.x * 256 + t;
    atomicAdd(&g_count[recv[e]], 1);          // N_EDGES % 256 == 0

    for (int idx = t; idx < 1024; idx += 256)
        ((float4*)sW)[idx] = ((const float4*)Wup)[idx];
    int n0 = blockIdx.x * 8;                  // 1250 * 8 = 10000
    if (t < 128)
        ((float4*)sN)[t] = ((const float4*)(nf + (size_t)n0 * 64))[t];
    __syncthreads();

#pragma unroll
    for (int j = 0; j < 2; ++j) {
        int o = t + j * 256;
        int row = o >> 6, c = o & 63;
        float a0 = 0.f, a1 = 0.f;
#pragma unroll
        for (int k = 0; k < 64; k += 2) {
            a0 = fmaf(sN[row * 64 + k],     sW[k * 64 + c],       a0);
            a1 = fmaf(sN[row * 64 + k + 1], sW[(k + 1) * 64 + c], a1);
        }
        g_h[(size_t)(n0 + row) * 64 + c] = (a0 + a1) * 0.125f;
    }
}

// ---------------- launch 2: parallel exclusive scan (+ zero g_count) ----------------
__global__ __launch_bounds__(1024) void k_scan() {
    __shared__ int warpsum[32];
    int t = threadIdx.x, lane = t & 31, w = t >> 5;
    int base = t * 10;
    int c[10];
    int s = 0;
#pragma unroll
    for (int i = 0; i < 10; ++i) {
        int idx = base + i;
        c[i] = (idx < N_NODES) ? g_count[idx] : 0;
        s += c[i];
    }
    int pre = s;
#pragma unroll
    for (int d = 1; d < 32; d <<= 1) {
        int v = __shfl_up_sync(0xffffffffu, pre, d);
        if (lane >= d) pre += v;
    }
    if (lane == 31) warpsum[w] = pre;
    __syncthreads();
    if (w == 0) {
        int v = warpsum[lane];
#pragma unroll
        for (int d = 1; d < 32; d <<= 1) {
            int u = __shfl_up_sync(0xffffffffu, v, d);
            if (lane >= d) v += u;
        }
        warpsum[lane] = v;
    }
    __syncthreads();
    int wbase = (w > 0) ? warpsum[w - 1] : 0;
    int run = wbase + pre - s;
#pragma unroll
    for (int i = 0; i < 10; ++i) {
        int idx = base + i;
        if (idx < N_NODES) {
            g_rowstart[idx] = run;
            g_cursor[idx] = run;
            run += c[i];
            g_count[idx] = 0;
        }
    }
    if (t == 1023) g_rowstart[N_NODES] = warpsum[31];
}

// ---------------- launch 3: CSR fill ----------------
__global__ void k_fill(const int* __restrict__ recv, const int* __restrict__ send) {
    int e = blockIdx.x * blockDim.x + threadIdx.x;
    if (e < N_EDGES) {
        int r = recv[e];
        int pos = atomicAdd(&g_cursor[r], 1);
        g_csr[pos] = e;
        g_send[pos] = send[e];
        g_recv[pos] = r;
    }
}

// ---------------- launch 4: fused MLP + SH + TP + segment scatter ----------------
// TE=128, 256 threads = 4 warp-pairs. Pair p owns rows [32p, 32p+32);
// warp-in-pair hb owns output cols [32hb, 32hb+32). All barriers pair-local.
// smem word offsets (19968 words = 79872 B -> 2 CTAs/SM)
#define O_ACT   0                 // [128][AP] tf32 activations, in place
#define O_MSG   9728              // [128][66] float
#define O_SSH   18176             // [128][12] float
#define O_RECV  19712             // [128] int
#define O_SEND  19840             // [128] int
#define SMEM_EDGE_WORDS 19968

#define BARP() asm volatile("bar.sync %0, 64;" :: "r"(p + 1) : "memory")

template <int KK>
__device__ __forceinline__ void mma2(const uint32_t* __restrict__ sAct, int base,
                                     float acc[2][4][4],
                                     int slab0, int hb, int gid, int tid4, int lane) {
#pragma unroll
    for (int s = 0; s < 2; ++s)
#pragma unroll
        for (int nt = 0; nt < 4; ++nt) {
            acc[s][nt][0] = 0.f; acc[s][nt][1] = 0.f;
            acc[s][nt][2] = 0.f; acc[s][nt][3] = 0.f;
        }
#pragma unroll
    for (int kk = 0; kk < KK; ++kk) {
        int c0 = kk * 8 + tid4;
        uint32_t a00 = sAct[(slab0 + gid) * AP + c0];
        uint32_t a01 = sAct[(slab0 + gid + 8) * AP + c0];
        uint32_t a02 = sAct[(slab0 + gid) * AP + c0 + 4];
        uint32_t a03 = sAct[(slab0 + gid + 8) * AP + c0 + 4];
        uint32_t a10 = sAct[(slab0 + 16 + gid) * AP + c0];
        uint32_t a11 = sAct[(slab0 + 24 + gid) * AP + c0];
        uint32_t a12 = sAct[(slab0 + 16 + gid) * AP + c0 + 4];
        uint32_t a13 = sAct[(slab0 + 24 + gid) * AP + c0 + 4];
        const uint2* wp = &g_wfrag[base + (size_t)(hb * KK * 4 + kk * 4) * 32 + lane];
#pragma unroll
        for (int nt = 0; nt < 4; ++nt) {
            uint2 b = __ldg(wp + nt * 32);
            mma_tf32(acc[0][nt], a00, a01, a02, a03, b.x, b.y);
            mma_tf32(acc[1][nt], a10, a11, a12, a13, b.x, b.y);
        }
    }
}

__device__ __forceinline__ void store_act2(uint32_t* __restrict__ sAct,
                                           float acc[2][4][4], float scale,
                                           int slab0, int hb, int gid, int tid4) {
#pragma unroll
    for (int s = 0; s < 2; ++s)
#pragma unroll
        for (int nt = 0; nt < 4; ++nt) {
            int col = hb * 32 + nt * 8 + 2 * tid4;
            int r0 = slab0 + s * 16 + gid;
            uint32_t t0 = f2tf32(silu_f(acc[s][nt][0] * scale));
            uint32_t t1 = f2tf32(silu_f(acc[s][nt][1] * scale));
            uint32_t t2 = f2tf32(silu_f(acc[s][nt][2] * scale));
            uint32_t t3 = f2tf32(silu_f(acc[s][nt][3] * scale));
            *(uint2*)(sAct + r0 * AP + col)       = make_uint2(t0, t1);
            *(uint2*)(sAct + (r0 + 8) * AP + col) = make_uint2(t2, t3);
        }
}

template <int D, int KOFF>
__device__ __forceinline__ void l4_chunk(const uint32_t* __restrict__ sAct,
                                         float* __restrict__ sMsg,
                                         const float* __restrict__ sSh,
                                         const int* __restrict__ sRecv,
                                         const float2 hf[2][4][2], int base,
                                         int p, int slab0, int hb, int gid, int tid4,
                                         int lane, int tl) {
    float acc[2][4][4];
    mma2<8>(sAct, base, acc, slab0, hb, gid, tid4, lane);

    const float S = 1.f / 256.f;   // 1/sqrt(64) / avg_neigh
#pragma unroll
    for (int s = 0; s < 2; ++s)
#pragma unroll
        for (int nt = 0; nt < 4; ++nt) {
            int col = hb * 32 + nt * 8 + 2 * tid4;
            int r0 = slab0 + s * 16 + gid;
            float2 h0 = hf[s][nt][0], h1 = hf[s][nt][1];
            *(float2*)(sMsg + r0 * 66 + col) =
                make_float2(acc[s][nt][0] * h0.x * S, acc[s][nt][1] * h0.y * S);
            *(float2*)(sMsg + (r0 + 8) * 66 + col) =
                make_float2(acc[s][nt][2] * h1.x * S, acc[s][nt][3] * h1.y * S);
        }
    BARP();

    // epilogue: thread tl = channel, 32 rows of the pair; segment reduction
    {
        int c = tl;
        int ncur = sRecv[slab0];
        float a[D];
#pragma unroll
        for (int k = 0; k < D; ++k) a[k] = 0.f;
#pragma unroll 8
        for (int r = 0; r < 32; ++r) {
            int row = slab0 + r;
            int n = sRecv[row];
            if (n != ncur) {
#pragma unroll
                for (int k = 0; k < D; ++k) {
                    atomicAdd(&g_agg[(size_t)(ncur * 9 + KOFF + k) * 64 + c], a[k]);
                    a[k] = 0.f;
                }
                ncur = n;
            }
            float m = sMsg[row * 66 + c];
#pragma unroll
            for (int k = 0; k < D; ++k)
                a[k] = fmaf(m, sSh[row * 12 + KOFF + k], a[k]);
        }
#pragma unroll
        for (int k = 0; k < D; ++k)
            atomicAdd(&g_agg[(size_t)(ncur * 9 + KOFF + k) * 64 + c], a[k]);
    }
    BARP();   // epilogue reads done before next chunk's msg store
}

__global__ __launch_bounds__(256, 2) void k_edge(const float* __restrict__ evec,
                                                 const float* __restrict__ rad) {
    extern __shared__ uint32_t sm[];
    uint32_t* sAct = sm + O_ACT;
    float* sMsg    = (float*)(sm + O_MSG);
    float* sSh     = (float*)(sm + O_SSH);
    int*   sRecv   = (int*)(sm + O_RECV);
    int*   sSend   = (int*)(sm + O_SEND);

    int t = threadIdx.x, lane = t & 31, warp = t >> 5;
    int p = warp >> 1, hb = warp & 1;
    int gid = lane >> 2, tid4 = lane & 3;
    int slab0 = p * 32;
    int tl = t & 63;
    int pos_base = blockIdx.x * TE;

    // pair-local init: rows [32p, 32p+32)
    {
        int row = slab0 + (tl >> 1);
        int half = tl & 1;
        int pos = pos_base + row;
        int e = g_csr[pos];
        const float4 r = *(const float4*)(rad + (size_t)e * 8 + half * 4);
        uint32_t* dst = sAct + row * AP + half * 4;
        dst[0] = f2tf32(r.x); dst[1] = f2tf32(r.y);
        dst[2] = f2tf32(r.z); dst[3] = f2tf32(r.w);
        if (half == 0) {
            sRecv[row] = g_recv[pos];
            sSend[row] = g_send[pos];
            float x = evec[(size_t)e * 3], y = evec[(size_t)e * 3 + 1],
                  z = evec[(size_t)e * 3 + 2];
            float rn = rsqrtf(x * x + y * y + z * z);
            x *= rn; y *= rn; z *= rn;
            const float c3  = 1.7320508075688772f;
            const float c15 = 3.872983346207417f;
            const float c5h = 1.118033988749895f;
            const float c15h= 1.9364916731037085f;
            float* o = sSh + row * 12;
            o[0] = 1.f;
            o[1] = c3 * x; o[2] = c3 * y; o[3] = c3 * z;
            o[4] = c15 * x * y; o[5] = c15 * y * z;
            o[6] = c5h * (3.f * z * z - 1.f);
            o[7] = c15 * x * z; o[8] = c15h * (x * x - y * y);
        }
    }
    BARP();

    float acc[2][4][4];

    // L1 [128,8]@[8,64]
    mma2<1>(sAct, U_W1, acc, slab0, hb, gid, tid4, lane);
    BARP();
    store_act2(sAct, acc, 0.35355339059327373f, slab0, hb, gid, tid4);
    BARP();
    // L2
    mma2<8>(sAct, U_W2, acc, slab0, hb, gid, tid4, lane);
    BARP();
    store_act2(sAct, acc, 0.125f, slab0, hb, gid, tid4);
    BARP();
    // L3
    mma2<8>(sAct, U_W3, acc, slab0, hb, gid, tid4, lane);
    BARP();
    store_act2(sAct, acc, 0.125f, slab0, hb, gid, tid4);
    BARP();

    // h fragments (held in registers across all 3 chunks)
    float2 hf[2][4][2];
#pragma unroll
    for (int s = 0; s < 2; ++s)
#pragma unroll
        for (int nt = 0; nt < 4; ++nt) {
            int col = hb * 32 + nt * 8 + 2 * tid4;
#pragma unroll
            for (int rp = 0; rp < 2; ++rp) {
                int row = slab0 + s * 16 + gid + rp * 8;
                hf[s][nt][rp] =
                    *(const float2*)(g_h + (size_t)sSend[row] * 64 + col);
            }
        }

    l4_chunk<1, 0>(sAct, sMsg, sSh, sRecv, hf, U_W4 + 0 * 2048,
                   p, slab0, hb, gid, tid4, lane, tl);
    l4_chunk<3, 1>(sAct, sMsg, sSh, sRecv, hf, U_W4 + 1 * 2048,
                   p, slab0, hb, gid, tid4, lane, tl);
    l4_chunk<5, 4>(sAct, sMsg, sSh, sRecv, hf, U_W4 + 2 * 2048,
                   p, slab0, hb, gid, tid4, lane, tl);
}

// ---------------- launch 5: linear_down, 16 nodes/block (also re-zeroes g_agg) ----------------
template <int D, int KOFF, int OFF>
__device__ __forceinline__ void down_part(const float* __restrict__ sAg,
                                          const float* __restrict__ wrow,
                                          float* __restrict__ outn, int dch) {
    float acc[D];
#pragma unroll
    for (int m = 0; m < D; ++m) acc[m] = 0.f;
#pragma unroll
    for (int c4 = 0; c4 < 16; ++c4) {
        float4 w = *(const float4*)(wrow + c4 * 4);
#pragma unroll
        for (int m = 0; m < D; ++m) {
            float4 a = *(const float4*)(sAg + (KOFF + m) * 64 + c4 * 4);
            acc[m] += a.x * w.x + a.y * w.y + a.z * w.z + a.w * w.w;
        }
    }
#pragma unroll
    for (int m = 0; m < D; ++m)
        outn[OFF + dch * D + m] = acc[m] * 0.125f;
}

__global__ __launch_bounds__(256) void k_down(const float* __restrict__ Wd,
                                              float* __restrict__ out) {
    extern __shared__ float smf[];
    float* sWt = smf;                 // [192][68] = 13056
    float* sAg = smf + 13056;         // 16*576 = 9216
    int t = threadIdx.x;
    for (int idx = t; idx < 3 * 4096; idx += 256) {
        int l = idx >> 12, rem = idx & 4095, c = rem >> 6, dch = rem & 63;
        sWt[(l * 64 + dch) * 68 + c] = Wd[idx];
    }
    int nb = blockIdx.x * 16;
    float4* aggb = (float4*)(g_agg + (size_t)nb * 576);
    for (int idx = t; idx < 2304; idx += 256) {      // 16*576/4
        ((float4*)sAg)[idx] = aggb[idx];
        aggb[idx] = make_float4(0.f, 0.f, 0.f, 0.f); // restore invariant
    }
    __syncthreads();
    if (t < 192) {
        int l = t >> 6, dch = t & 63;
        const float* wrow = sWt + t * 68;
#pragma unroll 1
        for (int i = 0; i < 16; ++i) {
            const float* ag = sAg + i * 576;
            float* outn = out + (size_t)(nb + i) * 576;
            if (l == 0)      down_part<1, 0, 0>(ag, wrow, outn, dch);
            else if (l == 1) down_part<3, 1, 64>(ag, wrow, outn, dch);
            else             down_part<5, 4, 256>(ag, wrow, outn, dch);
        }
    }
}

// ---------------- launch ----------------
extern "C" void kernel_launch(void* const* d_in, const int* in_sizes, int n_in,
                              void* d_out, int out_size) {
    const float* evec = (const float*)d_in[0];
    const float* nf   = (const float*)d_in[1];
    const float* rad  = (const float*)d_in[2];
    const int* senders   = (const int*)d_in[3];
    const int* receivers = (const int*)d_in[4];
    const float* Wup = (const float*)d_in[5];
    const float* W1  = (const float*)d_in[6];
    const float* W2  = (const float*)d_in[7];
    const float* W3  = (const float*)d_in[8];
    const float* W4  = (const float*)d_in[9];
    const float* Wd  = (const float*)d_in[10];
    float* out = (float*)d_out;

    const int SMEM_EDGE = SMEM_EDGE_WORDS * 4;        // 79872 B -> 2 CTAs/SM
    const int SMEM_DOWN = (13056 + 9216) * 4;         // 89088 B
    cudaFuncSetAttribute(k_edge, cudaFuncAttributeMaxDynamicSharedMemorySize, SMEM_EDGE);
    cudaFuncSetAttribute(k_down, cudaFuncAttributeMaxDynamicSharedMemorySize, SMEM_DOWN);

    k_prep<<<41, 256>>>(W1, W2, W3, W4);
    k_count_h<<<N_EDGES / 256, 256>>>(receivers, nf, Wup);
    k_scan<<<1, 1024>>>();
    k_fill<<<N_EDGES / 256, 256>>>(receivers, senders);
    k_edge<<<N_EDGES / TE, 256, SMEM_EDGE>>>(evec, rad);
    k_down<<<N_NODES / 16, 256, SMEM_DOWN>>>(Wd, out);
}

// round 7
// speedup vs baseline: 2.3061x; 1.0206x over previous
#include <cuda_runtime.h>
#include <cstdint>

#define N_NODES 10000
#define N_EDGES 320000

// ---------------- scratch (device globals; allocation-free) ----------------
__device__ float g_h[N_NODES * 64];                 // 2.56 MB
__device__ float g_agg[(size_t)N_NODES * 576];      // 23 MB; zeroed by k_down after read
__device__ int   g_count[N_NODES];                  // zeroed by k_scan after read
__device__ int   g_rowstart[N_NODES + 1];
__device__ int   g_cursor[N_NODES];
__device__ int   g_csr[N_EDGES];
__device__ int   g_send[N_EDGES];
__device__ int   g_recv[N_EDGES];
__device__ uint2 g_wfrag[10496];                    // fragment-ordered tf32 weights (84KB)

// uint2 offsets into g_wfrag
#define U_W1 0
#define U_W2 256
#define U_W3 2304
#define U_W4 4352       // + chunk*2048

__device__ __forceinline__ float silu_f(float x) {
    return x / (1.f + __expf(-x));
}

__device__ __forceinline__ uint32_t f2tf32(float f) {
    uint32_t r;
    asm("cvt.rna.tf32.f32 %0, %1;" : "=r"(r) : "f"(f));
    return r;
}

__device__ __forceinline__ void mma_tf32(float acc[4], uint32_t a0, uint32_t a1,
                                         uint32_t a2, uint32_t a3,
                                         uint32_t b0, uint32_t b1) {
    asm volatile(
        "mma.sync.aligned.m16n8k8.row.col.f32.tf32.tf32.f32 "
        "{%0,%1,%2,%3}, {%4,%5,%6,%7}, {%8,%9}, {%0,%1,%2,%3};\n"
        : "+f"(acc[0]), "+f"(acc[1]), "+f"(acc[2]), "+f"(acc[3])
        : "r"(a0), "r"(a1), "r"(a2), "r"(a3), "r"(b0), "r"(b1));
}

// ---------------- launch 0: pre-convert weights into fragment order ----------------
__global__ void k_prep(const float* __restrict__ W1, const float* __restrict__ W2,
                       const float* __restrict__ W3, const float* __restrict__ W4) {
    int u = blockIdx.x * 256 + threadIdx.x;
    if (u >= 10496) return;
    const float* src; int rs, co, KK, local;
    if (u < 256)       { src = W1; rs = 64;  co = 0;   KK = 1; local = u; }
    else if (u < 2304) { src = W2; rs = 64;  co = 0;   KK = 8; local = u - 256; }
    else if (u < 4352) { src = W3; rs = 64;  co = 0;   KK = 8; local = u - 2304; }
    else if (u < 6400) { src = W4; rs = 192; co = 0;   KK = 8; local = u - 4352; }
    else if (u < 8448) { src = W4; rs = 192; co = 64;  KK = 8; local = u - 6400; }
    else               { src = W4; rs = 192; co = 128; KK = 8; local = u - 8448; }
    int lane = local & 31; int rest = local >> 5;
    int nt = rest & 3; rest >>= 2;
    int kk = rest % KK; int hb = rest / KK;
    int n = co + hb * 32 + nt * 8 + (lane >> 2);
    int k0 = kk * 8 + (lane & 3);
    g_wfrag[u] = make_uint2(f2tf32(src[(size_t)k0 * rs + n]),
                            f2tf32(src[(size_t)(k0 + 4) * rs + n]));
}

// ---------------- launch 1: edge count histogram + h = (nf @ W_up)/8 ----------------
__global__ __launch_bounds__(256) void k_count_h(const int* __restrict__ recv,
                                                 const float* __restrict__ nf,
                                                 const float* __restrict__ Wup) {
    __shared__ float sW[64 * 64];
    __shared__ float sN[8 * 64];
    int t = threadIdx.x;
    int e = blockIdx.x * 256 + t;
    atomicAdd(&g_count[recv[e]], 1);          // N_EDGES % 256 == 0

    for (int idx = t; idx < 1024; idx += 256)
        ((float4*)sW)[idx] = ((const float4*)Wup)[idx];
    int n0 = blockIdx.x * 8;                  // 1250 * 8 = 10000
    if (t < 128)
        ((float4*)sN)[t] = ((const float4*)(nf + (size_t)n0 * 64))[t];
    __syncthreads();

#pragma unroll
    for (int j = 0; j < 2; ++j) {
        int o = t + j * 256;
        int row = o >> 6, c = o & 63;
        float a0 = 0.f, a1 = 0.f;
#pragma unroll
        for (int k = 0; k < 64; k += 2) {
            a0 = fmaf(sN[row * 64 + k],     sW[k * 64 + c],       a0);
            a1 = fmaf(sN[row * 64 + k + 1], sW[(k + 1) * 64 + c], a1);
        }
        g_h[(size_t)(n0 + row) * 64 + c] = (a0 + a1) * 0.125f;
    }
}

// ---------------- launch 2: parallel exclusive scan (+ zero g_count) ----------------
__global__ __launch_bounds__(1024) void k_scan() {
    __shared__ int warpsum[32];
    int t = threadIdx.x, lane = t & 31, w = t >> 5;
    int base = t * 10;
    int c[10];
    int s = 0;
#pragma unroll
    for (int i = 0; i < 10; ++i) {
        int idx = base + i;
        c[i] = (idx < N_NODES) ? g_count[idx] : 0;
        s += c[i];
    }
    int pre = s;
#pragma unroll
    for (int d = 1; d < 32; d <<= 1) {
        int v = __shfl_up_sync(0xffffffffu, pre, d);
        if (lane >= d) pre += v;
    }
    if (lane == 31) warpsum[w] = pre;
    __syncthreads();
    if (w == 0) {
        int v = warpsum[lane];
#pragma unroll
        for (int d = 1; d < 32; d <<= 1) {
            int u = __shfl_up_sync(0xffffffffu, v, d);
            if (lane >= d) v += u;
        }
        warpsum[lane] = v;
    }
    __syncthreads();
    int wbase = (w > 0) ? warpsum[w - 1] : 0;
    int run = wbase + pre - s;
#pragma unroll
    for (int i = 0; i < 10; ++i) {
        int idx = base + i;
        if (idx < N_NODES) {
            g_rowstart[idx] = run;
            g_cursor[idx] = run;
            run += c[i];
            g_count[idx] = 0;
        }
    }
    if (t == 1023) g_rowstart[N_NODES] = warpsum[31];
}

// ---------------- launch 3: CSR fill ----------------
__global__ void k_fill(const int* __restrict__ recv, const int* __restrict__ send) {
    int e = blockIdx.x * blockDim.x + threadIdx.x;
    if (e < N_EDGES) {
        int r = recv[e];
        int pos = atomicAdd(&g_cursor[r], 1);
        g_csr[pos] = e;
        g_send[pos] = send[e];
        g_recv[pos] = r;
    }
}

// ---------------- launch 4: warp-autonomous fused MLP + SH + TP + scatter ----------------
// Each warp owns 16 CSR positions end-to-end; activations stay in registers
// between layers (C-frag -> A-frag shuffle conversion); no block barriers.

// Convert layer output (C frags, 8 n-tiles) into next layer's A frags, applying
// scale + silu + tf32 rounding. C: (gid,2q),(gid,2q+1),(gid+8,2q),(gid+8,2q+1).
// A: (gid,q),(gid+8,q),(gid,q+4),(gid+8,q+4). Source lane = 4*gid + (q>>1) [+2].
__device__ __forceinline__ void cvt_frag(const float acc[8][4], float scale,
                                         uint32_t A0[8], uint32_t A1[8],
                                         uint32_t A2[8], uint32_t A3[8],
                                         int lane, int tid4) {
    int src  = (lane & 28) | (tid4 >> 1);
    int src2 = src + 2;
    bool odd = (tid4 & 1);
#pragma unroll
    for (int j = 0; j < 8; ++j) {
        uint32_t c0 = f2tf32(silu_f(acc[j][0] * scale));
        uint32_t c1 = f2tf32(silu_f(acc[j][1] * scale));
        uint32_t c2 = f2tf32(silu_f(acc[j][2] * scale));
        uint32_t c3 = f2tf32(silu_f(acc[j][3] * scale));
        uint32_t s0 = __shfl_sync(0xffffffffu, c0, src);
        uint32_t s1 = __shfl_sync(0xffffffffu, c1, src);
        uint32_t s2 = __shfl_sync(0xffffffffu, c2, src);
        uint32_t s3 = __shfl_sync(0xffffffffu, c3, src);
        uint32_t u0 = __shfl_sync(0xffffffffu, c0, src2);
        uint32_t u1 = __shfl_sync(0xffffffffu, c1, src2);
        uint32_t u2 = __shfl_sync(0xffffffffu, c2, src2);
        uint32_t u3 = __shfl_sync(0xffffffffu, c3, src2);
        A0[j] = odd ? s1 : s0;
        A1[j] = odd ? s3 : s2;
        A2[j] = odd ? u1 : u0;
        A3[j] = odd ? u3 : u2;
    }
}

// 64-col layer: acc[j] over 8 n-tiles, K=64 (8 kk steps)
__device__ __forceinline__ void layer64(int base, const uint32_t A0[8],
                                        const uint32_t A1[8], const uint32_t A2[8],
                                        const uint32_t A3[8], float acc[8][4],
                                        int lane) {
#pragma unroll
    for (int j = 0; j < 8; ++j) {
        acc[j][0] = 0.f; acc[j][1] = 0.f; acc[j][2] = 0.f; acc[j][3] = 0.f;
    }
#pragma unroll
    for (int kk = 0; kk < 8; ++kk) {
#pragma unroll
        for (int j = 0; j < 8; ++j) {
            uint2 b = __ldg(&g_wfrag[base + ((j >> 2) * 32 + kk * 4 + (j & 3)) * 32 + lane]);
            mma_tf32(acc[j], A0[kk], A1[kk], A2[kk], A3[kk], b.x, b.y);
        }
    }
}

template <int D, int KOFF>
__device__ __forceinline__ void l4_chunk(int base, const uint32_t A0[8],
                                         const uint32_t A1[8], const uint32_t A2[8],
                                         const uint32_t A3[8],
                                         const float2 hf0[8], const float2 hf1[8],
                                         float* __restrict__ wMsg,
                                         const float* __restrict__ wSh,
                                         const int* __restrict__ wRecv,
                                         int lane, int gid, int tid4) {
    float acc[8][4];
    layer64(base, A0, A1, A2, A3, acc, lane);

    const float S = 1.f / 256.f;   // 1/sqrt(64) / avg_neigh
#pragma unroll
    for (int j = 0; j < 8; ++j) {
        int col = j * 8 + 2 * tid4;
        *(float2*)(wMsg + gid * 66 + col) =
            make_float2(acc[j][0] * hf0[j].x * S, acc[j][1] * hf0[j].y * S);
        *(float2*)(wMsg + (gid + 8) * 66 + col) =
            make_float2(acc[j][2] * hf1[j].x * S, acc[j][3] * hf1[j].y * S);
    }
    __syncwarp();

    // warp-local segment reduction: lane handles channels (lane) and (lane+32)
    {
        int ncur = wRecv[0];
        float a[D], b[D];
#pragma unroll
        for (int k = 0; k < D; ++k) { a[k] = 0.f; b[k] = 0.f; }
#pragma unroll 4
        for (int r = 0; r < 16; ++r) {
            int n = wRecv[r];
            if (n != ncur) {
#pragma unroll
                for (int k = 0; k < D; ++k) {
                    atomicAdd(&g_agg[(size_t)(ncur * 9 + KOFF + k) * 64 + lane], a[k]);
                    atomicAdd(&g_agg[(size_t)(ncur * 9 + KOFF + k) * 64 + 32 + lane], b[k]);
                    a[k] = 0.f; b[k] = 0.f;
                }
                ncur = n;
            }
            float m0 = wMsg[r * 66 + lane];
            float m1 = wMsg[r * 66 + 32 + lane];
#pragma unroll
            for (int k = 0; k < D; ++k) {
                float s = wSh[r * 12 + KOFF + k];
                a[k] = fmaf(m0, s, a[k]);
                b[k] = fmaf(m1, s, b[k]);
            }
        }
#pragma unroll
        for (int k = 0; k < D; ++k) {
            atomicAdd(&g_agg[(size_t)(ncur * 9 + KOFF + k) * 64 + lane], a[k]);
            atomicAdd(&g_agg[(size_t)(ncur * 9 + KOFF + k) * 64 + 32 + lane], b[k]);
        }
    }
    __syncwarp();
}

__global__ __launch_bounds__(256, 2) void k_edge(const float* __restrict__ evec,
                                                 const float* __restrict__ rad) {
    __shared__ float sMsgAll[8][16 * 66];     // 33792 B
    __shared__ float sShAll[8][16 * 12];      // 6144 B
    __shared__ int   sMeta[8][32];            // 1024 B

    int t = threadIdx.x, lane = t & 31, warp = t >> 5;
    int gid = lane >> 2, tid4 = lane & 3;
    float* wMsg = sMsgAll[warp];
    float* wSh  = sShAll[warp];
    int* wRecv  = sMeta[warp];
    int* wSend  = sMeta[warp] + 16;
    int pos0 = blockIdx.x * 128 + warp * 16;

    // init: lanes 0..15 handle one row each (SH + meta)
    if (lane < 16) {
        int pos = pos0 + lane;
        int e = g_csr[pos];
        wRecv[lane] = g_recv[pos];
        wSend[lane] = g_send[pos];
        float x = evec[(size_t)e * 3], y = evec[(size_t)e * 3 + 1],
              z = evec[(size_t)e * 3 + 2];
        float rn = rsqrtf(x * x + y * y + z * z);
        x *= rn; y *= rn; z *= rn;
        const float c3  = 1.7320508075688772f;
        const float c15 = 3.872983346207417f;
        const float c5h = 1.118033988749895f;
        const float c15h= 1.9364916731037085f;
        float* o = wSh + lane * 12;
        o[0] = 1.f;
        o[1] = c3 * x; o[2] = c3 * y; o[3] = c3 * z;
        o[4] = c15 * x * y; o[5] = c15 * y * z;
        o[6] = c5h * (3.f * z * z - 1.f);
        o[7] = c15 * x * z; o[8] = c15h * (x * x - y * y);
    }
    __syncwarp();

    // L1 A-fragments straight from rad (rows gid, gid+8; cols tid4, tid4+4)
    int e0 = g_csr[pos0 + gid], e1 = g_csr[pos0 + gid + 8];
    uint32_t r0 = f2tf32(__ldg(rad + (size_t)e0 * 8 + tid4));
    uint32_t r1 = f2tf32(__ldg(rad + (size_t)e1 * 8 + tid4));
    uint32_t r2 = f2tf32(__ldg(rad + (size_t)e0 * 8 + tid4 + 4));
    uint32_t r3 = f2tf32(__ldg(rad + (size_t)e1 * 8 + tid4 + 4));

    float acc[8][4];
    uint32_t A0[8], A1[8], A2[8], A3[8];

    // L1: [16,8]@[8,64]
#pragma unroll
    for (int j = 0; j < 8; ++j) {
        acc[j][0] = 0.f; acc[j][1] = 0.f; acc[j][2] = 0.f; acc[j][3] = 0.f;
    }
#pragma unroll
    for (int j = 0; j < 8; ++j) {
        uint2 b = __ldg(&g_wfrag[U_W1 + j * 32 + lane]);
        mma_tf32(acc[j], r0, r1, r2, r3, b.x, b.y);
    }
    cvt_frag(acc, 0.35355339059327373f, A0, A1, A2, A3, lane, tid4);

    // L2
    layer64(U_W2, A0, A1, A2, A3, acc, lane);
    cvt_frag(acc, 0.125f, A0, A1, A2, A3, lane, tid4);

    // L3
    layer64(U_W3, A0, A1, A2, A3, acc, lane);
    cvt_frag(acc, 0.125f, A0, A1, A2, A3, lane, tid4);

    // h fragments (register-resident across all 3 chunks)
    int s0r = wSend[gid], s1r = wSend[gid + 8];
    float2 hf0[8], hf1[8];
#pragma unroll
    for (int j = 0; j < 8; ++j) {
        hf0[j] = *(const float2*)(g_h + (size_t)s0r * 64 + j * 8 + 2 * tid4);
        hf1[j] = *(const float2*)(g_h + (size_t)s1r * 64 + j * 8 + 2 * tid4);
    }

    // L4 chunks + tensor product + warp-local segment scatter
    l4_chunk<1, 0>(U_W4 + 0 * 2048, A0, A1, A2, A3, hf0, hf1,
                   wMsg, wSh, wRecv, lane, gid, tid4);
    l4_chunk<3, 1>(U_W4 + 1 * 2048, A0, A1, A2, A3, hf0, hf1,
                   wMsg, wSh, wRecv, lane, gid, tid4);
    l4_chunk<5, 4>(U_W4 + 2 * 2048, A0, A1, A2, A3, hf0, hf1,
                   wMsg, wSh, wRecv, lane, gid, tid4);
}

// ---------------- launch 5: linear_down, 16 nodes/block (also re-zeroes g_agg) ----------------
template <int D, int KOFF, int OFF>
__device__ __forceinline__ void down_part(const float* __restrict__ sAg,
                                          const float* __restrict__ wrow,
                                          float* __restrict__ outn, int dch) {
    float acc[D];
#pragma unroll
    for (int m = 0; m < D; ++m) acc[m] = 0.f;
#pragma unroll
    for (int c4 = 0; c4 < 16; ++c4) {
        float4 w = *(const float4*)(wrow + c4 * 4);
#pragma unroll
        for (int m = 0; m < D; ++m) {
            float4 a = *(const float4*)(sAg + (KOFF + m) * 64 + c4 * 4);
            acc[m] += a.x * w.x + a.y * w.y + a.z * w.z + a.w * w.w;
        }
    }
#pragma unroll
    for (int m = 0; m < D; ++m)
        outn[OFF + dch * D + m] = acc[m] * 0.125f;
}

__global__ __launch_bounds__(256) void k_down(const float* __restrict__ Wd,
                                              float* __restrict__ out) {
    extern __shared__ float smf[];
    float* sWt = smf;                 // [192][68] = 13056
    float* sAg = smf + 13056;         // 16*576 = 9216
    int t = threadIdx.x;
    for (int idx = t; idx < 3 * 4096; idx += 256) {
        int l = idx >> 12, rem = idx & 4095, c = rem >> 6, dch = rem & 63;
        sWt[(l * 64 + dch) * 68 + c] = Wd[idx];
    }
    int nb = blockIdx.x * 16;
    float4* aggb = (float4*)(g_agg + (size_t)nb * 576);
    for (int idx = t; idx < 2304; idx += 256) {      // 16*576/4
        ((float4*)sAg)[idx] = aggb[idx];
        aggb[idx] = make_float4(0.f, 0.f, 0.f, 0.f); // restore invariant
    }
    __syncthreads();
    if (t < 192) {
        int l = t >> 6, dch = t & 63;
        const float* wrow = sWt + t * 68;
#pragma unroll 1
        for (int i = 0; i < 16; ++i) {
            const float* ag = sAg + i * 576;
            float* outn = out + (size_t)(nb + i) * 576;
            if (l == 0)      down_part<1, 0, 0>(ag, wrow, outn, dch);
            else if (l == 1) down_part<3, 1, 64>(ag, wrow, outn, dch);
            else             down_part<5, 4, 256>(ag, wrow, outn, dch);
        }
    }
}

// ---------------- launch ----------------
extern "C" void kernel_launch(void* const* d_in, const int* in_sizes, int n_in,
                              void* d_out, int out_size) {
    const float* evec = (const float*)d_in[0];
    const float* nf   = (const float*)d_in[1];
    const float* rad  = (const float*)d_in[2];
    const int* senders   = (const int*)d_in[3];
    const int* receivers = (const int*)d_in[4];
    const float* Wup = (const float*)d_in[5];
    const float* W1  = (const float*)d_in[6];
    const float* W2  = (const float*)d_in[7];
    const float* W3  = (const float*)d_in[8];
    const float* W4  = (const float*)d_in[9];
    const float* Wd  = (const float*)d_in[10];
    float* out = (float*)d_out;

    const int SMEM_DOWN = (13056 + 9216) * 4;         // 89088 B
    cudaFuncSetAttribute(k_down, cudaFuncAttributeMaxDynamicSharedMemorySize, SMEM_DOWN);

    k_prep<<<41, 256>>>(W1, W2, W3, W4);
    k_count_h<<<N_EDGES / 256, 256>>>(receivers, nf, Wup);
    k_scan<<<1, 1024>>>();
    k_fill<<<N_EDGES / 256, 256>>>(receivers, senders);
    k_edge<<<N_EDGES / 128, 256>>>(evec, rad);
    k_down<<<N_NODES / 16, 256, SMEM_DOWN>>>(Wd, out);
}